// round 3
// baseline (speedup 1.0000x reference)
#include <cuda_runtime.h>
#include <math.h>

// Problem constants
#define Bb 16
#define Ss 128
#define Ee 512
#define Hh 1024
#define G4 4096
#define Vv 32000

// ---------------- static scratch (no allocations allowed) ----------------
__device__ float g_x[2048 * 512];     // embedded inputs [T*B, E]
__device__ float g_pre[2048 * 4096];  // precomputed input gates + bias [T*B, 4H]
__device__ float g_seq[2048 * 1024];  // layer output sequence [T*B, H]
__device__ float g_hA[16 * 1024];
__device__ float g_hB[16 * 1024];
__device__ float g_c[16 * 1024];
__device__ float g_h0f[16 * 1024];
__device__ float g_c0f[16 * 1024];
__device__ float g_h1f[16 * 1024];
__device__ float g_c1f[16 * 1024];

// ---------------- tiny utility kernels ----------------
__global__ void zero_kernel(float* __restrict__ p, int n) {
    int i = blockIdx.x * blockDim.x + threadIdx.x;
    if (i < n) p[i] = 0.0f;
}

__global__ void copy_kernel(float* __restrict__ dst, const float* __restrict__ src, int n) {
    int i = blockIdx.x * blockDim.x + threadIdx.x;
    if (i < n) dst[i] = src[i];
}

// zero out[:, 0, :]  (out is [B, S, V])
__global__ void zero_t0_kernel(float* __restrict__ out) {
    int i = blockIdx.x * blockDim.x + threadIdx.x;
    if (i < Bb * Vv) {
        int m = i / Vv;
        int n = i - m * Vv;
        out[(size_t)m * Ss * Vv + n] = 0.0f;
    }
}

// Embedding gather: out[(t*B+m)*E + e] = emb[tok[m*S + t]*E + e], t in [0,T)
__global__ void gather_kernel(const int* __restrict__ tok, const float* __restrict__ emb,
                              float* __restrict__ out, int T) {
    int idx = blockIdx.x * blockDim.x + threadIdx.x;  // float4 index
    int total = T * Bb * (Ee / 4);
    if (idx >= total) return;
    int e4 = idx & (Ee / 4 - 1);  // 0..127
    int r = idx >> 7;             // row t*B+m
    int m = r & (Bb - 1);
    int t = r >> 4;
    int token = tok[m * Ss + t];
    *(float4*)(out + (size_t)r * Ee + e4 * 4) =
        *(const float4*)(emb + (size_t)token * Ee + e4 * 4);
}

// ---------------- SGEMM: C = A[M,K] * W[N,K]^T + bias ----------------
// mode 0: C[r, n] = ...   (C stride N)
// mode 1: scatter into output: row = (r%B)*S + (r/B) + 1   (C stride N = V)
#define BM 128
#define BN 128
#define BK 16

__global__ __launch_bounds__(256) void sgemm_bias_kernel(
    const float* __restrict__ A, const float* __restrict__ W,
    const float* __restrict__ bias, float* __restrict__ C,
    int M, int N, int K, int mode) {
    __shared__ float As[BK][BM + 4];
    __shared__ float Bs[BK][BN + 4];

    int tid = threadIdx.x;
    int tx = tid & 15;
    int ty = tid >> 4;
    int m0 = blockIdx.y * BM;
    int n0 = blockIdx.x * BN;

    float acc[8][8];
#pragma unroll
    for (int i = 0; i < 8; i++)
#pragma unroll
        for (int j = 0; j < 8; j++) acc[i][j] = 0.0f;

    for (int kt = 0; kt < K; kt += BK) {
#pragma unroll
        for (int i = 0; i < 2; i++) {
            int fidx = tid + i * 256;     // 0..511
            int rr = fidx >> 2;           // 0..127
            int kq = (fidx & 3) * 4;      // 0,4,8,12
            float4 v = make_float4(0.f, 0.f, 0.f, 0.f);
            int gr = m0 + rr;
            if (gr < M) v = *(const float4*)(A + (size_t)gr * K + kt + kq);
            As[kq + 0][rr] = v.x; As[kq + 1][rr] = v.y;
            As[kq + 2][rr] = v.z; As[kq + 3][rr] = v.w;
            float4 u = make_float4(0.f, 0.f, 0.f, 0.f);
            int gn = n0 + rr;
            if (gn < N) u = *(const float4*)(W + (size_t)gn * K + kt + kq);
            Bs[kq + 0][rr] = u.x; Bs[kq + 1][rr] = u.y;
            Bs[kq + 2][rr] = u.z; Bs[kq + 3][rr] = u.w;
        }
        __syncthreads();
#pragma unroll
        for (int kk = 0; kk < BK; kk++) {
            float a[8], b[8];
            *(float4*)&a[0] = *(const float4*)&As[kk][ty * 8];
            *(float4*)&a[4] = *(const float4*)&As[kk][ty * 8 + 4];
            *(float4*)&b[0] = *(const float4*)&Bs[kk][tx * 8];
            *(float4*)&b[4] = *(const float4*)&Bs[kk][tx * 8 + 4];
#pragma unroll
            for (int i = 0; i < 8; i++)
#pragma unroll
                for (int j = 0; j < 8; j++) acc[i][j] = fmaf(a[i], b[j], acc[i][j]);
        }
        __syncthreads();
    }

#pragma unroll
    for (int i = 0; i < 8; i++) {
        int gr = m0 + ty * 8 + i;
        if (gr >= M) continue;
        int orow;
        if (mode == 1) {
            int m = gr & (Bb - 1);
            int t = gr >> 4;
            orow = m * Ss + t + 1;
        } else {
            orow = gr;
        }
        float* crow = C + (size_t)orow * N;
#pragma unroll
        for (int j = 0; j < 8; j++) {
            int gn = n0 + tx * 8 + j;
            if (gn < N) crow[gn] = acc[i][j] + bias[gn];
        }
    }
}

// ---------------- fused LSTM step ----------------
// grid = 128 blocks (8 hidden indices each), 256 threads.
// Thread layout: row = tid>>3 in [0,32) covers (gate g=row>>3, jj=row&7),
//                mp = tid&7 covers m pair (2*mp, 2*mp+1).
// Computes gates = pre_t + h_in * Whh^T, then activations + state update.
__global__ __launch_bounds__(256) void lstm_step_kernel(
    const float* __restrict__ pre,   // [B, 4H] for this timestep
    const float* __restrict__ Whh,   // [4H, H]
    const float* __restrict__ h_in,  // [B, H]
    float* __restrict__ h_out,       // [B, H]
    float* __restrict__ c,           // [B, H] in/out
    float* __restrict__ y)           // [B, H] or nullptr
{
    int tid = threadIdx.x;
    int row = tid >> 3;      // 0..31
    int mp = tid & 7;        // 0..7
    int g = row >> 3;        // 0..3
    int jj = row & 7;        // 0..7
    int j0 = blockIdx.x * 8;

    const float* wrow = Whh + (size_t)(g * Hh + j0 + jj) * Hh;
    const float* h0p = h_in + (size_t)(2 * mp) * Hh;
    const float* h1p = h_in + (size_t)(2 * mp + 1) * Hh;

    float acc0 = 0.f, acc1 = 0.f;
#pragma unroll 4
    for (int k = 0; k < Hh; k += 4) {
        float4 w = *(const float4*)(wrow + k);
        float4 a = *(const float4*)(h0p + k);
        float4 b = *(const float4*)(h1p + k);
        acc0 = fmaf(w.x, a.x, acc0); acc0 = fmaf(w.y, a.y, acc0);
        acc0 = fmaf(w.z, a.z, acc0); acc0 = fmaf(w.w, a.w, acc0);
        acc1 = fmaf(w.x, b.x, acc1); acc1 = fmaf(w.y, b.y, acc1);
        acc1 = fmaf(w.z, b.z, acc1); acc1 = fmaf(w.w, b.w, acc1);
    }

    __shared__ float red[32][17];
    red[row][2 * mp] = acc0;
    red[row][2 * mp + 1] = acc1;
    __syncthreads();

    if (tid < 128) {
        int m = tid & 15;
        int jr = tid >> 4;       // 0..7
        int j = j0 + jr;
        const float* pm = pre + (size_t)m * G4;
        float pi = pm[0 * Hh + j] + red[jr][m];
        float pf = pm[1 * Hh + j] + red[8 + jr][m];
        float pg = pm[2 * Hh + j] + red[16 + jr][m];
        float po = pm[3 * Hh + j] + red[24 + jr][m];
        float iv = 1.0f / (1.0f + expf(-pi));
        float fv = 1.0f / (1.0f + expf(-pf));
        float gv = tanhf(pg);
        float ov = 1.0f / (1.0f + expf(-po));
        int idx = m * Hh + j;
        float cn = fv * c[idx] + iv * gv;
        float hn = ov * tanhf(cn);
        c[idx] = cn;
        h_out[idx] = hn;
        if (y) y[idx] = hn;
    }
}

// ---------------- host orchestration ----------------
static inline void sgemm(const float* A, const float* W, const float* bias, float* C,
                         int M, int N, int K, int mode) {
    dim3 grid(N / BN, (M + BM - 1) / BM);
    sgemm_bias_kernel<<<grid, 256>>>(A, W, bias, C, M, N, K, mode);
}

extern "C" void kernel_launch(void* const* d_in, const int* in_sizes, int n_in,
                              void* d_out, int out_size) {
    const int* src = (const int*)d_in[0];
    const int* trg = (const int*)d_in[1];
    const float* enc_emb = (const float*)d_in[2];
    const float* dec_emb = (const float*)d_in[3];
    const float* enc_Wih0 = (const float*)d_in[4];
    const float* enc_Whh0 = (const float*)d_in[5];
    const float* enc_b0 = (const float*)d_in[6];
    const float* enc_Wih1 = (const float*)d_in[7];
    const float* enc_Whh1 = (const float*)d_in[8];
    const float* enc_b1 = (const float*)d_in[9];
    const float* dec_Wih0 = (const float*)d_in[10];
    const float* dec_Whh0 = (const float*)d_in[11];
    const float* dec_b0 = (const float*)d_in[12];
    const float* dec_Wih1 = (const float*)d_in[13];
    const float* dec_Whh1 = (const float*)d_in[14];
    const float* dec_b1 = (const float*)d_in[15];
    const float* fc_W = (const float*)d_in[16];
    const float* fc_b = (const float*)d_in[17];
    float* out = (float*)d_out;

    float *x, *pre, *seq, *hA, *hB, *cb, *h0f, *c0f, *h1f, *c1f;
    cudaGetSymbolAddress((void**)&x, g_x);
    cudaGetSymbolAddress((void**)&pre, g_pre);
    cudaGetSymbolAddress((void**)&seq, g_seq);
    cudaGetSymbolAddress((void**)&hA, g_hA);
    cudaGetSymbolAddress((void**)&hB, g_hB);
    cudaGetSymbolAddress((void**)&cb, g_c);
    cudaGetSymbolAddress((void**)&h0f, g_h0f);
    cudaGetSymbolAddress((void**)&c0f, g_c0f);
    cudaGetSymbolAddress((void**)&h1f, g_h1f);
    cudaGetSymbolAddress((void**)&c1f, g_c1f);

    float* hbuf[2] = {hA, hB};
    const int NST = Bb * Hh;  // 16384 state elems

    // ================= ENCODER layer 0 =================
    {
        int total = Ss * Bb * (Ee / 4);
        gather_kernel<<<(total + 255) / 256, 256>>>(src, enc_emb, x, Ss);
    }
    sgemm(x, enc_Wih0, enc_b0, pre, Bb * Ss, G4, Ee, 0);
    zero_kernel<<<(NST + 255) / 256, 256>>>(hA, NST);
    zero_kernel<<<(NST + 255) / 256, 256>>>(cb, NST);
    for (int t = 0; t < Ss; t++) {
        lstm_step_kernel<<<128, 256>>>(pre + (size_t)t * Bb * G4, enc_Whh0,
                                       hbuf[t & 1], hbuf[(t + 1) & 1], cb,
                                       seq + (size_t)t * Bb * Hh);
    }
    // final state after 128 steps lives in hbuf[0]
    copy_kernel<<<(NST + 255) / 256, 256>>>(h0f, hbuf[0], NST);
    copy_kernel<<<(NST + 255) / 256, 256>>>(c0f, cb, NST);

    // ================= ENCODER layer 1 (only final state needed) =================
    sgemm(seq, enc_Wih1, enc_b1, pre, Bb * Ss, G4, Hh, 0);
    zero_kernel<<<(NST + 255) / 256, 256>>>(hA, NST);
    zero_kernel<<<(NST + 255) / 256, 256>>>(cb, NST);
    for (int t = 0; t < Ss; t++) {
        lstm_step_kernel<<<128, 256>>>(pre + (size_t)t * Bb * G4, enc_Whh1,
                                       hbuf[t & 1], hbuf[(t + 1) & 1], cb, (float*)0);
    }
    copy_kernel<<<(NST + 255) / 256, 256>>>(h1f, hbuf[0], NST);
    copy_kernel<<<(NST + 255) / 256, 256>>>(c1f, cb, NST);

    // ================= DECODER layer 0 (T = 127) =================
    const int Td = Ss - 1;
    {
        int total = Td * Bb * (Ee / 4);
        gather_kernel<<<(total + 255) / 256, 256>>>(trg, dec_emb, x, Td);
    }
    sgemm(x, dec_Wih0, dec_b0, pre, Bb * Td, G4, Ee, 0);
    copy_kernel<<<(NST + 255) / 256, 256>>>(hA, h0f, NST);
    copy_kernel<<<(NST + 255) / 256, 256>>>(cb, c0f, NST);
    for (int t = 0; t < Td; t++) {
        lstm_step_kernel<<<128, 256>>>(pre + (size_t)t * Bb * G4, dec_Whh0,
                                       hbuf[t & 1], hbuf[(t + 1) & 1], cb,
                                       seq + (size_t)t * Bb * Hh);
    }

    // ================= DECODER layer 1 =================
    sgemm(seq, dec_Wih1, dec_b1, pre, Bb * Td, G4, Hh, 0);
    copy_kernel<<<(NST + 255) / 256, 256>>>(hA, h1f, NST);
    copy_kernel<<<(NST + 255) / 256, 256>>>(cb, c1f, NST);
    for (int t = 0; t < Td; t++) {
        lstm_step_kernel<<<128, 256>>>(pre + (size_t)t * Bb * G4, dec_Whh1,
                                       hbuf[t & 1], hbuf[(t + 1) & 1], cb,
                                       seq + (size_t)t * Bb * Hh);
    }

    // ================= Classifier: out[:,1+t,:] = d1 @ fc_W^T + fc_b =================
    zero_t0_kernel<<<(Bb * Vv + 255) / 256, 256>>>(out);
    sgemm(seq, fc_W, fc_b, out, Bb * Td, Vv, Hh, 1);
}

// round 5
// speedup vs baseline: 1.0787x; 1.0787x over previous
#include <cuda_runtime.h>
#include <cuda_bf16.h>
#include <math.h>
#include <stdint.h>

// Problem constants
#define Bb 16
#define Ss 128
#define Ee 512
#define Hh 1024
#define G4 4096
#define Vv 32000

// ---------------- static scratch (no allocations allowed) ----------------
__device__ float g_pre[2048 * 4096];         // precomputed input gates + bias [T*B, 4H]
__device__ float g_seq[2048 * 1024];         // layer output sequence [T*B, H]
__device__ __nv_bfloat16 g_ah[2048 * 1024];  // A operand hi
__device__ __nv_bfloat16 g_al[2048 * 1024];  // A operand lo
__device__ __nv_bfloat16 g_wh[32000 * 1024]; // W operand hi (reused per GEMM)
__device__ __nv_bfloat16 g_wl[32000 * 1024]; // W operand lo
__device__ float g_hA[16 * 1024];
__device__ float g_hB[16 * 1024];
__device__ float g_c[16 * 1024];
__device__ float g_h0f[16 * 1024];
__device__ float g_c0f[16 * 1024];
__device__ float g_h1f[16 * 1024];
__device__ float g_c1f[16 * 1024];

// ---------------- PTX helpers ----------------
__device__ __forceinline__ uint32_t smem_u32(const void* p) {
    uint32_t a;
    asm("{ .reg .u64 t; cvta.to.shared.u64 t, %1; cvt.u32.u64 %0, t; }" : "=r"(a) : "l"(p));
    return a;
}

__device__ __forceinline__ void cp16(uint32_t dst, const void* src, int sz) {
    asm volatile("cp.async.cg.shared.global [%0], [%1], 16, %2;"
                 :: "r"(dst), "l"(src), "r"(sz) : "memory");
}

#define LDSM4(r0, r1, r2, r3, addr) \
    asm volatile("ldmatrix.sync.aligned.m8n8.x4.shared.b16 {%0,%1,%2,%3}, [%4];" \
                 : "=r"(r0), "=r"(r1), "=r"(r2), "=r"(r3) : "r"(addr))

#define MMA16816(c, a0, a1, a2, a3, b0, b1) \
    asm volatile("mma.sync.aligned.m16n8k16.row.col.f32.bf16.bf16.f32 " \
                 "{%0,%1,%2,%3}, {%4,%5,%6,%7}, {%8,%9}, {%0,%1,%2,%3};" \
                 : "+f"((c)[0]), "+f"((c)[1]), "+f"((c)[2]), "+f"((c)[3]) \
                 : "r"(a0), "r"(a1), "r"(a2), "r"(a3), "r"(b0), "r"(b1))

// ---------------- tiny utility kernels ----------------
__global__ void zero_kernel(float* __restrict__ p, int n) {
    int i = blockIdx.x * blockDim.x + threadIdx.x;
    if (i < n) p[i] = 0.0f;
}

__global__ void copy_kernel(float* __restrict__ dst, const float* __restrict__ src, int n) {
    int i = blockIdx.x * blockDim.x + threadIdx.x;
    if (i < n) dst[i] = src[i];
}

__global__ void zero_t0_kernel(float* __restrict__ out) {
    int i = blockIdx.x * blockDim.x + threadIdx.x;
    if (i < Bb * Vv) {
        int m = i / Vv;
        int n = i - m * Vv;
        out[(size_t)m * Ss * Vv + n] = 0.0f;
    }
}

// split fp32 -> bf16 hi + bf16 lo (vec4)
__global__ void split4_kernel(const float* __restrict__ in, __nv_bfloat16* __restrict__ hi,
                              __nv_bfloat16* __restrict__ lo, int n4) {
    int i = blockIdx.x * blockDim.x + threadIdx.x;
    if (i >= n4) return;
    float4 v = ((const float4*)in)[i];
    __nv_bfloat16 h0 = __float2bfloat16(v.x);
    __nv_bfloat16 h1 = __float2bfloat16(v.y);
    __nv_bfloat16 h2 = __float2bfloat16(v.z);
    __nv_bfloat16 h3 = __float2bfloat16(v.w);
    __nv_bfloat162* H = (__nv_bfloat162*)hi;
    __nv_bfloat162* L = (__nv_bfloat162*)lo;
    H[2 * i + 0] = __nv_bfloat162(h0, h1);
    H[2 * i + 1] = __nv_bfloat162(h2, h3);
    L[2 * i + 0] = __nv_bfloat162(__float2bfloat16(v.x - __bfloat162float(h0)),
                                  __float2bfloat16(v.y - __bfloat162float(h1)));
    L[2 * i + 1] = __nv_bfloat162(__float2bfloat16(v.z - __bfloat162float(h2)),
                                  __float2bfloat16(v.w - __bfloat162float(h3)));
}

// Embedding gather + bf16 split: out rows [(t*B+m), E]
__global__ void gather_split_kernel(const int* __restrict__ tok, const float* __restrict__ emb,
                                    __nv_bfloat16* __restrict__ hi, __nv_bfloat16* __restrict__ lo,
                                    int T) {
    int idx = blockIdx.x * blockDim.x + threadIdx.x;  // float2 index
    int total = T * Bb * (Ee / 2);
    if (idx >= total) return;
    int e2 = idx & (Ee / 2 - 1);
    int r = idx >> 8;
    int m = r & (Bb - 1);
    int t = r >> 4;
    int token = tok[m * Ss + t];
    float2 v = *(const float2*)(emb + (size_t)token * Ee + e2 * 2);
    __nv_bfloat16 h0 = __float2bfloat16(v.x);
    __nv_bfloat16 h1 = __float2bfloat16(v.y);
    ((__nv_bfloat162*)hi)[(size_t)r * (Ee / 2) + e2] = __nv_bfloat162(h0, h1);
    ((__nv_bfloat162*)lo)[(size_t)r * (Ee / 2) + e2] =
        __nv_bfloat162(__float2bfloat16(v.x - __bfloat162float(h0)),
                       __float2bfloat16(v.y - __bfloat162float(h1)));
}

// ---------------- mma.sync split-bf16 GEMM ----------------
// C[M,N] = (Ah+Al)[M,K] * (Bh+Bl)[N,K]^T + bias  (3-term split, fp32 acc)
// mode 0: C row = r; mode 1: scatter row = (r%B)*Ss + r/B + 1 (classifier).
// CTA tile 128x128, warp tile 64x64 (4 warps), BK=32, cp.async double-buffered.
#define RSB 80            // smem row stride in bytes (32 bf16 data + 16B pad)
#define TILE_BYTES (128 * RSB)       // 10240
#define STAGE_BYTES (4 * TILE_BYTES) // 40960 (Ah, Al, Bh, Bl)
#define GEMM_SMEM (2 * STAGE_BYTES)  // 81920

__device__ __forceinline__ void load_stage_mma(
    uint32_t base, const __nv_bfloat16* __restrict__ Ah, const __nv_bfloat16* __restrict__ Al,
    const __nv_bfloat16* __restrict__ Bh, const __nv_bfloat16* __restrict__ Bl,
    int m0, int n0, int M, int K, int kc, int tid) {
    int k0 = kc * 32;
#pragma unroll
    for (int i = 0; i < 4; i++) {
        int chunk = tid + (i << 7);   // 0..511
        int row = chunk >> 2;         // 0..127
        int c4 = chunk & 3;           // 16B chunk within row
        uint32_t smoff = row * RSB + c4 * 16;
        int gk = k0 + c4 * 8;
        int gm = m0 + row;
        int oka = (gm < M);
        size_t aoff = (size_t)(oka ? gm : 0) * K + gk;
        cp16(base + smoff, Ah + aoff, oka ? 16 : 0);
        cp16(base + TILE_BYTES + smoff, Al + aoff, oka ? 16 : 0);
        size_t boff = (size_t)(n0 + row) * K + gk;
        cp16(base + 2 * TILE_BYTES + smoff, Bh + boff, 16);
        cp16(base + 3 * TILE_BYTES + smoff, Bl + boff, 16);
    }
}

__global__ __launch_bounds__(128) void gemm_mma_kernel(
    const __nv_bfloat16* __restrict__ Ah, const __nv_bfloat16* __restrict__ Al,
    const __nv_bfloat16* __restrict__ Bh, const __nv_bfloat16* __restrict__ Bl,
    const float* __restrict__ bias, float* __restrict__ C,
    int M, int N, int K, int mode) {
    extern __shared__ char smem[];
    uint32_t sb = smem_u32(smem);
    int tid = threadIdx.x;
    int lane = tid & 31;
    int warp = tid >> 5;
    int wm = (warp >> 1) * 64;
    int wn = (warp & 1) * 64;
    int m0 = blockIdx.y * 128;
    int n0 = blockIdx.x * 128;

    float acc[4][8][4];
#pragma unroll
    for (int i = 0; i < 4; i++)
#pragma unroll
        for (int j = 0; j < 8; j++)
#pragma unroll
            for (int q = 0; q < 4; q++) acc[i][j][q] = 0.0f;

    const int NC = K >> 5;  // stages of BK=32

    load_stage_mma(sb, Ah, Al, Bh, Bl, m0, n0, M, K, 0, tid);
    asm volatile("cp.async.commit_group;" ::: "memory");

    // per-lane ldmatrix address components (within a k16 sub-tile)
    uint32_t a_row = wm + (lane & 15);            // + mi*16
    uint32_t a_kb = (lane >> 4) * 16;             // 16B chunk
    uint32_t b_row = wn + (lane & 7) + ((lane >> 4) << 3);  // + ni*16
    uint32_t b_kb = ((lane >> 3) & 1) * 16;

    for (int kc = 0; kc < NC; kc++) {
        if (kc + 1 < NC) {
            load_stage_mma(sb + ((kc + 1) & 1) * STAGE_BYTES, Ah, Al, Bh, Bl, m0, n0, M, K,
                           kc + 1, tid);
            asm volatile("cp.async.commit_group;" ::: "memory");
            asm volatile("cp.async.wait_group 1;" ::: "memory");
        } else {
            asm volatile("cp.async.wait_group 0;" ::: "memory");
        }
        __syncthreads();
        uint32_t stage = sb + (kc & 1) * STAGE_BYTES;
#pragma unroll
        for (int kk = 0; kk < 2; kk++) {
            uint32_t kbyte = kk * 32;  // 16 bf16
            uint32_t a[4][4];
            // --- Ah fragments ---
#pragma unroll
            for (int mi = 0; mi < 4; mi++) {
                uint32_t ad = stage + (a_row + mi * 16) * RSB + kbyte + a_kb;
                LDSM4(a[mi][0], a[mi][1], a[mi][2], a[mi][3], ad);
            }
            // --- Ah*Bh and Ah*Bl ---
#pragma unroll
            for (int ni = 0; ni < 4; ni++) {
                uint32_t b0, b1, b2, b3;
                uint32_t bd = stage + 2 * TILE_BYTES + (b_row + ni * 16) * RSB + kbyte + b_kb;
                LDSM4(b0, b1, b2, b3, bd);
#pragma unroll
                for (int mi = 0; mi < 4; mi++) {
                    MMA16816(acc[mi][ni * 2], a[mi][0], a[mi][1], a[mi][2], a[mi][3], b0, b1);
                    MMA16816(acc[mi][ni * 2 + 1], a[mi][0], a[mi][1], a[mi][2], a[mi][3], b2, b3);
                }
                uint32_t ld = stage + 3 * TILE_BYTES + (b_row + ni * 16) * RSB + kbyte + b_kb;
                LDSM4(b0, b1, b2, b3, ld);
#pragma unroll
                for (int mi = 0; mi < 4; mi++) {
                    MMA16816(acc[mi][ni * 2], a[mi][0], a[mi][1], a[mi][2], a[mi][3], b0, b1);
                    MMA16816(acc[mi][ni * 2 + 1], a[mi][0], a[mi][1], a[mi][2], a[mi][3], b2, b3);
                }
            }
            // --- Al fragments, Al*Bh ---
#pragma unroll
            for (int mi = 0; mi < 4; mi++) {
                uint32_t ad = stage + TILE_BYTES + (a_row + mi * 16) * RSB + kbyte + a_kb;
                LDSM4(a[mi][0], a[mi][1], a[mi][2], a[mi][3], ad);
            }
#pragma unroll
            for (int ni = 0; ni < 4; ni++) {
                uint32_t b0, b1, b2, b3;
                uint32_t bd = stage + 2 * TILE_BYTES + (b_row + ni * 16) * RSB + kbyte + b_kb;
                LDSM4(b0, b1, b2, b3, bd);
#pragma unroll
                for (int mi = 0; mi < 4; mi++) {
                    MMA16816(acc[mi][ni * 2], a[mi][0], a[mi][1], a[mi][2], a[mi][3], b0, b1);
                    MMA16816(acc[mi][ni * 2 + 1], a[mi][0], a[mi][1], a[mi][2], a[mi][3], b2, b3);
                }
            }
        }
        __syncthreads();
    }

    // epilogue: c frag (mi,nj): rows wm+mi*16+(lane>>2), +8; cols wn+nj*8+2*(lane&3)
    int rbase = m0 + wm + (lane >> 2);
    int cbase = n0 + wn + 2 * (lane & 3);
#pragma unroll
    for (int mi = 0; mi < 4; mi++) {
#pragma unroll
        for (int half = 0; half < 2; half++) {
            int m = rbase + mi * 16 + half * 8;
            if (m >= M) continue;
            int orow = mode ? ((m & (Bb - 1)) * Ss + (m >> 4) + 1) : m;
            float* crow = C + (size_t)orow * N;
#pragma unroll
            for (int nj = 0; nj < 8; nj++) {
                int n = cbase + nj * 8;
                float2 v;
                v.x = acc[mi][nj][half * 2 + 0] + bias[n];
                v.y = acc[mi][nj][half * 2 + 1] + bias[n + 1];
                *(float2*)(crow + n) = v;
            }
        }
    }
}

// ---------------- fused LSTM step ----------------
__global__ __launch_bounds__(256) void lstm_step_kernel(
    const float* __restrict__ pre, const float* __restrict__ Whh,
    const float* __restrict__ h_in, float* __restrict__ h_out,
    float* __restrict__ c, float* __restrict__ y) {
    int tid = threadIdx.x;
    int row = tid >> 3;
    int mp = tid & 7;
    int g = row >> 3;
    int jj = row & 7;
    int j0 = blockIdx.x * 8;

    const float* wrow = Whh + (size_t)(g * Hh + j0 + jj) * Hh;
    const float* h0p = h_in + (size_t)(2 * mp) * Hh;
    const float* h1p = h_in + (size_t)(2 * mp + 1) * Hh;

    float acc0 = 0.f, acc1 = 0.f;
#pragma unroll 4
    for (int k = 0; k < Hh; k += 4) {
        float4 w = *(const float4*)(wrow + k);
        float4 a = *(const float4*)(h0p + k);
        float4 b = *(const float4*)(h1p + k);
        acc0 = fmaf(w.x, a.x, acc0); acc0 = fmaf(w.y, a.y, acc0);
        acc0 = fmaf(w.z, a.z, acc0); acc0 = fmaf(w.w, a.w, acc0);
        acc1 = fmaf(w.x, b.x, acc1); acc1 = fmaf(w.y, b.y, acc1);
        acc1 = fmaf(w.z, b.z, acc1); acc1 = fmaf(w.w, b.w, acc1);
    }

    __shared__ float red[32][17];
    red[row][2 * mp] = acc0;
    red[row][2 * mp + 1] = acc1;
    __syncthreads();

    if (tid < 128) {
        int m = tid & 15;
        int jr = tid >> 4;
        int j = j0 + jr;
        const float* pm = pre + (size_t)m * G4;
        float pi = pm[0 * Hh + j] + red[jr][m];
        float pf = pm[1 * Hh + j] + red[8 + jr][m];
        float pg = pm[2 * Hh + j] + red[16 + jr][m];
        float po = pm[3 * Hh + j] + red[24 + jr][m];
        float iv = 1.0f / (1.0f + expf(-pi));
        float fv = 1.0f / (1.0f + expf(-pf));
        float gv = tanhf(pg);
        float ov = 1.0f / (1.0f + expf(-po));
        int idx = m * Hh + j;
        float cn = fv * c[idx] + iv * gv;
        float hn = ov * tanhf(cn);
        c[idx] = cn;
        h_out[idx] = hn;
        if (y) y[idx] = hn;
    }
}

// ---------------- host orchestration ----------------
static inline void split_w(const float* w, __nv_bfloat16* hi, __nv_bfloat16* lo, int n) {
    int n4 = n / 4;
    split4_kernel<<<(n4 + 255) / 256, 256>>>(w, hi, lo, n4);
}

static inline void gemm_tc(const __nv_bfloat16* Ah, const __nv_bfloat16* Al,
                           const __nv_bfloat16* Bh, const __nv_bfloat16* Bl,
                           const float* bias, float* C, int M, int N, int K, int mode) {
    dim3 grid(N / 128, (M + 127) / 128);
    gemm_mma_kernel<<<grid, 128, GEMM_SMEM>>>(Ah, Al, Bh, Bl, bias, C, M, N, K, mode);
}

extern "C" void kernel_launch(void* const* d_in, const int* in_sizes, int n_in,
                              void* d_out, int out_size) {
    const int* src = (const int*)d_in[0];
    const int* trg = (const int*)d_in[1];
    const float* enc_emb = (const float*)d_in[2];
    const float* dec_emb = (const float*)d_in[3];
    const float* enc_Wih0 = (const float*)d_in[4];
    const float* enc_Whh0 = (const float*)d_in[5];
    const float* enc_b0 = (const float*)d_in[6];
    const float* enc_Wih1 = (const float*)d_in[7];
    const float* enc_Whh1 = (const float*)d_in[8];
    const float* enc_b1 = (const float*)d_in[9];
    const float* dec_Wih0 = (const float*)d_in[10];
    const float* dec_Whh0 = (const float*)d_in[11];
    const float* dec_b0 = (const float*)d_in[12];
    const float* dec_Wih1 = (const float*)d_in[13];
    const float* dec_Whh1 = (const float*)d_in[14];
    const float* dec_b1 = (const float*)d_in[15];
    const float* fc_W = (const float*)d_in[16];
    const float* fc_b = (const float*)d_in[17];
    float* out = (float*)d_out;

    cudaFuncSetAttribute(gemm_mma_kernel, cudaFuncAttributeMaxDynamicSharedMemorySize,
                         GEMM_SMEM);

    float *pre, *seq, *hA, *hB, *cb, *h0f, *c0f, *h1f, *c1f;
    __nv_bfloat16 *ah, *al, *wh, *wl;
    cudaGetSymbolAddress((void**)&pre, g_pre);
    cudaGetSymbolAddress((void**)&seq, g_seq);
    cudaGetSymbolAddress((void**)&ah, g_ah);
    cudaGetSymbolAddress((void**)&al, g_al);
    cudaGetSymbolAddress((void**)&wh, g_wh);
    cudaGetSymbolAddress((void**)&wl, g_wl);
    cudaGetSymbolAddress((void**)&hA, g_hA);
    cudaGetSymbolAddress((void**)&hB, g_hB);
    cudaGetSymbolAddress((void**)&cb, g_c);
    cudaGetSymbolAddress((void**)&h0f, g_h0f);
    cudaGetSymbolAddress((void**)&c0f, g_c0f);
    cudaGetSymbolAddress((void**)&h1f, g_h1f);
    cudaGetSymbolAddress((void**)&c1f, g_c1f);

    float* hbuf[2] = {hA, hB};
    const int NST = Bb * Hh;

    // ================= ENCODER layer 0 =================
    {
        int total = Ss * Bb * (Ee / 2);
        gather_split_kernel<<<(total + 255) / 256, 256>>>(src, enc_emb, ah, al, Ss);
    }
    split_w(enc_Wih0, wh, wl, G4 * Ee);
    gemm_tc(ah, al, wh, wl, enc_b0, pre, Bb * Ss, G4, Ee, 0);
    zero_kernel<<<(NST + 255) / 256, 256>>>(hA, NST);
    zero_kernel<<<(NST + 255) / 256, 256>>>(cb, NST);
    for (int t = 0; t < Ss; t++) {
        lstm_step_kernel<<<128, 256>>>(pre + (size_t)t * Bb * G4, enc_Whh0,
                                       hbuf[t & 1], hbuf[(t + 1) & 1], cb,
                                       seq + (size_t)t * Bb * Hh);
    }
    copy_kernel<<<(NST + 255) / 256, 256>>>(h0f, hbuf[0], NST);
    copy_kernel<<<(NST + 255) / 256, 256>>>(c0f, cb, NST);

    // ================= ENCODER layer 1 (only final state needed) =================
    split_w(seq, ah, al, Bb * Ss * Hh);
    split_w(enc_Wih1, wh, wl, G4 * Hh);
    gemm_tc(ah, al, wh, wl, enc_b1, pre, Bb * Ss, G4, Hh, 0);
    zero_kernel<<<(NST + 255) / 256, 256>>>(hA, NST);
    zero_kernel<<<(NST + 255) / 256, 256>>>(cb, NST);
    for (int t = 0; t < Ss; t++) {
        lstm_step_kernel<<<128, 256>>>(pre + (size_t)t * Bb * G4, enc_Whh1,
                                       hbuf[t & 1], hbuf[(t + 1) & 1], cb, (float*)0);
    }
    copy_kernel<<<(NST + 255) / 256, 256>>>(h1f, hbuf[0], NST);
    copy_kernel<<<(NST + 255) / 256, 256>>>(c1f, cb, NST);

    // ================= DECODER layer 0 (T = 127) =================
    const int Td = Ss - 1;
    {
        int total = Td * Bb * (Ee / 2);
        gather_split_kernel<<<(total + 255) / 256, 256>>>(trg, dec_emb, ah, al, Td);
    }
    split_w(dec_Wih0, wh, wl, G4 * Ee);
    gemm_tc(ah, al, wh, wl, dec_b0, pre, Bb * Td, G4, Ee, 0);
    copy_kernel<<<(NST + 255) / 256, 256>>>(hA, h0f, NST);
    copy_kernel<<<(NST + 255) / 256, 256>>>(cb, c0f, NST);
    for (int t = 0; t < Td; t++) {
        lstm_step_kernel<<<128, 256>>>(pre + (size_t)t * Bb * G4, dec_Whh0,
                                       hbuf[t & 1], hbuf[(t + 1) & 1], cb,
                                       seq + (size_t)t * Bb * Hh);
    }

    // ================= DECODER layer 1 =================
    split_w(seq, ah, al, Bb * Td * Hh);
    split_w(dec_Wih1, wh, wl, G4 * Hh);
    gemm_tc(ah, al, wh, wl, dec_b1, pre, Bb * Td, G4, Hh, 0);
    copy_kernel<<<(NST + 255) / 256, 256>>>(hA, h1f, NST);
    copy_kernel<<<(NST + 255) / 256, 256>>>(cb, c1f, NST);
    for (int t = 0; t < Td; t++) {
        lstm_step_kernel<<<128, 256>>>(pre + (size_t)t * Bb * G4, dec_Whh1,
                                       hbuf[t & 1], hbuf[(t + 1) & 1], cb,
                                       seq + (size_t)t * Bb * Hh);
    }

    // ================= Classifier =================
    split_w(seq, ah, al, Bb * Td * Hh);
    split_w(fc_W, wh, wl, Vv * Hh);
    zero_t0_kernel<<<(Bb * Vv + 255) / 256, 256>>>(out);
    gemm_tc(ah, al, wh, wl, fc_b, out, Bb * Td, Vv, Hh, 1);
}

// round 7
// speedup vs baseline: 3.0013x; 2.7822x over previous
#include <cuda_runtime.h>
#include <cuda_bf16.h>
#include <math.h>
#include <stdint.h>

// Problem constants
#define Bb 16
#define Ss 128
#define Ee 512
#define Hh 1024
#define G4 4096
#define Vv 32000

// ---------------- static scratch (no allocations allowed) ----------------
__device__ float g_pre[2048 * 4096];         // precomputed input gates + bias [T*B, 4H]
__device__ float g_seq[2048 * 1024];         // layer output sequence [T*B, H]
__device__ __nv_bfloat16 g_ah[2048 * 1024];  // A operand hi
__device__ __nv_bfloat16 g_al[2048 * 1024];  // A operand lo
__device__ __nv_bfloat16 g_wh[32000 * 1024]; // W operand hi (reused per GEMM)
__device__ __nv_bfloat16 g_wl[32000 * 1024]; // W operand lo
__device__ float g_hA[16 * 1024];
__device__ float g_hB[16 * 1024];
__device__ float g_c[16 * 1024];
__device__ float g_h0f[16 * 1024];
__device__ float g_c0f[16 * 1024];
__device__ float g_h1f[16 * 1024];
__device__ float g_c1f[16 * 1024];
__device__ unsigned g_bar;

// ---------------- PTX helpers ----------------
__device__ __forceinline__ uint32_t smem_u32(const void* p) {
    uint32_t a;
    asm("{ .reg .u64 t; cvta.to.shared.u64 t, %1; cvt.u32.u64 %0, t; }" : "=r"(a) : "l"(p));
    return a;
}

__device__ __forceinline__ void cp16(uint32_t dst, const void* src, int sz) {
    asm volatile("cp.async.cg.shared.global [%0], [%1], 16, %2;"
                 :: "r"(dst), "l"(src), "r"(sz) : "memory");
}

#define LDSM4(r0, r1, r2, r3, addr) \
    asm volatile("ldmatrix.sync.aligned.m8n8.x4.shared.b16 {%0,%1,%2,%3}, [%4];" \
                 : "=r"(r0), "=r"(r1), "=r"(r2), "=r"(r3) : "r"(addr))

#define MMA16816(c, a0, a1, a2, a3, b0, b1) \
    asm volatile("mma.sync.aligned.m16n8k16.row.col.f32.bf16.bf16.f32 " \
                 "{%0,%1,%2,%3}, {%4,%5,%6,%7}, {%8,%9}, {%0,%1,%2,%3};" \
                 : "+f"((c)[0]), "+f"((c)[1]), "+f"((c)[2]), "+f"((c)[3]) \
                 : "r"(a0), "r"(a1), "r"(a2), "r"(a3), "r"(b0), "r"(b1))

// ---------------- tiny utility kernels ----------------
__global__ void zero_kernel(float* __restrict__ p, int n) {
    int i = blockIdx.x * blockDim.x + threadIdx.x;
    if (i < n) p[i] = 0.0f;
}

__global__ void zero_bar_kernel() { g_bar = 0u; }

__global__ void copy_kernel(float* __restrict__ dst, const float* __restrict__ src, int n) {
    int i = blockIdx.x * blockDim.x + threadIdx.x;
    if (i < n) dst[i] = src[i];
}

__global__ void zero_t0_kernel(float* __restrict__ out) {
    int i = blockIdx.x * blockDim.x + threadIdx.x;
    if (i < Bb * Vv) {
        int m = i / Vv;
        int n = i - m * Vv;
        out[(size_t)m * Ss * Vv + n] = 0.0f;
    }
}

// split fp32 -> bf16 hi + bf16 lo (vec4)
__global__ void split4_kernel(const float* __restrict__ in, __nv_bfloat16* __restrict__ hi,
                              __nv_bfloat16* __restrict__ lo, int n4) {
    int i = blockIdx.x * blockDim.x + threadIdx.x;
    if (i >= n4) return;
    float4 v = ((const float4*)in)[i];
    __nv_bfloat16 h0 = __float2bfloat16(v.x);
    __nv_bfloat16 h1 = __float2bfloat16(v.y);
    __nv_bfloat16 h2 = __float2bfloat16(v.z);
    __nv_bfloat16 h3 = __float2bfloat16(v.w);
    __nv_bfloat162* H = (__nv_bfloat162*)hi;
    __nv_bfloat162* L = (__nv_bfloat162*)lo;
    H[2 * i + 0] = __nv_bfloat162(h0, h1);
    H[2 * i + 1] = __nv_bfloat162(h2, h3);
    L[2 * i + 0] = __nv_bfloat162(__float2bfloat16(v.x - __bfloat162float(h0)),
                                  __float2bfloat16(v.y - __bfloat162float(h1)));
    L[2 * i + 1] = __nv_bfloat162(__float2bfloat16(v.z - __bfloat162float(h2)),
                                  __float2bfloat16(v.w - __bfloat162float(h3)));
}

// Embedding gather + bf16 split: out rows [(t*B+m), E]
__global__ void gather_split_kernel(const int* __restrict__ tok, const float* __restrict__ emb,
                                    __nv_bfloat16* __restrict__ hi, __nv_bfloat16* __restrict__ lo,
                                    int T) {
    int idx = blockIdx.x * blockDim.x + threadIdx.x;  // float2 index
    int total = T * Bb * (Ee / 2);
    if (idx >= total) return;
    int e2 = idx & (Ee / 2 - 1);
    int r = idx >> 8;
    int m = r & (Bb - 1);
    int t = r >> 4;
    int token = tok[m * Ss + t];
    float2 v = *(const float2*)(emb + (size_t)token * Ee + e2 * 2);
    __nv_bfloat16 h0 = __float2bfloat16(v.x);
    __nv_bfloat16 h1 = __float2bfloat16(v.y);
    ((__nv_bfloat162*)hi)[(size_t)r * (Ee / 2) + e2] = __nv_bfloat162(h0, h1);
    ((__nv_bfloat162*)lo)[(size_t)r * (Ee / 2) + e2] =
        __nv_bfloat162(__float2bfloat16(v.x - __bfloat162float(h0)),
                       __float2bfloat16(v.y - __bfloat162float(h1)));
}

// ---------------- mma.sync split-bf16 GEMM (unchanged from R5) ----------------
#define RSB 80
#define TILE_BYTES (128 * RSB)
#define STAGE_BYTES (4 * TILE_BYTES)
#define GEMM_SMEM (2 * STAGE_BYTES)

__device__ __forceinline__ void load_stage_mma(
    uint32_t base, const __nv_bfloat16* __restrict__ Ah, const __nv_bfloat16* __restrict__ Al,
    const __nv_bfloat16* __restrict__ Bh, const __nv_bfloat16* __restrict__ Bl,
    int m0, int n0, int M, int K, int kc, int tid) {
    int k0 = kc * 32;
#pragma unroll
    for (int i = 0; i < 4; i++) {
        int chunk = tid + (i << 7);
        int row = chunk >> 2;
        int c4 = chunk & 3;
        uint32_t smoff = row * RSB + c4 * 16;
        int gk = k0 + c4 * 8;
        int gm = m0 + row;
        int oka = (gm < M);
        size_t aoff = (size_t)(oka ? gm : 0) * K + gk;
        cp16(base + smoff, Ah + aoff, oka ? 16 : 0);
        cp16(base + TILE_BYTES + smoff, Al + aoff, oka ? 16 : 0);
        size_t boff = (size_t)(n0 + row) * K + gk;
        cp16(base + 2 * TILE_BYTES + smoff, Bh + boff, 16);
        cp16(base + 3 * TILE_BYTES + smoff, Bl + boff, 16);
    }
}

__global__ __launch_bounds__(128) void gemm_mma_kernel(
    const __nv_bfloat16* __restrict__ Ah, const __nv_bfloat16* __restrict__ Al,
    const __nv_bfloat16* __restrict__ Bh, const __nv_bfloat16* __restrict__ Bl,
    const float* __restrict__ bias, float* __restrict__ C,
    int M, int N, int K, int mode) {
    extern __shared__ char smem[];
    uint32_t sb = smem_u32(smem);
    int tid = threadIdx.x;
    int lane = tid & 31;
    int warp = tid >> 5;
    int wm = (warp >> 1) * 64;
    int wn = (warp & 1) * 64;
    int m0 = blockIdx.y * 128;
    int n0 = blockIdx.x * 128;

    float acc[4][8][4];
#pragma unroll
    for (int i = 0; i < 4; i++)
#pragma unroll
        for (int j = 0; j < 8; j++)
#pragma unroll
            for (int q = 0; q < 4; q++) acc[i][j][q] = 0.0f;

    const int NC = K >> 5;

    load_stage_mma(sb, Ah, Al, Bh, Bl, m0, n0, M, K, 0, tid);
    asm volatile("cp.async.commit_group;" ::: "memory");

    uint32_t a_row = wm + (lane & 15);
    uint32_t a_kb = (lane >> 4) * 16;
    uint32_t b_row = wn + (lane & 7) + ((lane >> 4) << 3);
    uint32_t b_kb = ((lane >> 3) & 1) * 16;

    for (int kc = 0; kc < NC; kc++) {
        if (kc + 1 < NC) {
            load_stage_mma(sb + ((kc + 1) & 1) * STAGE_BYTES, Ah, Al, Bh, Bl, m0, n0, M, K,
                           kc + 1, tid);
            asm volatile("cp.async.commit_group;" ::: "memory");
            asm volatile("cp.async.wait_group 1;" ::: "memory");
        } else {
            asm volatile("cp.async.wait_group 0;" ::: "memory");
        }
        __syncthreads();
        uint32_t stage = sb + (kc & 1) * STAGE_BYTES;
#pragma unroll
        for (int kk = 0; kk < 2; kk++) {
            uint32_t kbyte = kk * 32;
            uint32_t a[4][4];
#pragma unroll
            for (int mi = 0; mi < 4; mi++) {
                uint32_t ad = stage + (a_row + mi * 16) * RSB + kbyte + a_kb;
                LDSM4(a[mi][0], a[mi][1], a[mi][2], a[mi][3], ad);
            }
#pragma unroll
            for (int ni = 0; ni < 4; ni++) {
                uint32_t b0, b1, b2, b3;
                uint32_t bd = stage + 2 * TILE_BYTES + (b_row + ni * 16) * RSB + kbyte + b_kb;
                LDSM4(b0, b1, b2, b3, bd);
#pragma unroll
                for (int mi = 0; mi < 4; mi++) {
                    MMA16816(acc[mi][ni * 2], a[mi][0], a[mi][1], a[mi][2], a[mi][3], b0, b1);
                    MMA16816(acc[mi][ni * 2 + 1], a[mi][0], a[mi][1], a[mi][2], a[mi][3], b2, b3);
                }
                uint32_t ld = stage + 3 * TILE_BYTES + (b_row + ni * 16) * RSB + kbyte + b_kb;
                LDSM4(b0, b1, b2, b3, ld);
#pragma unroll
                for (int mi = 0; mi < 4; mi++) {
                    MMA16816(acc[mi][ni * 2], a[mi][0], a[mi][1], a[mi][2], a[mi][3], b0, b1);
                    MMA16816(acc[mi][ni * 2 + 1], a[mi][0], a[mi][1], a[mi][2], a[mi][3], b2, b3);
                }
            }
#pragma unroll
            for (int mi = 0; mi < 4; mi++) {
                uint32_t ad = stage + TILE_BYTES + (a_row + mi * 16) * RSB + kbyte + a_kb;
                LDSM4(a[mi][0], a[mi][1], a[mi][2], a[mi][3], ad);
            }
#pragma unroll
            for (int ni = 0; ni < 4; ni++) {
                uint32_t b0, b1, b2, b3;
                uint32_t bd = stage + 2 * TILE_BYTES + (b_row + ni * 16) * RSB + kbyte + b_kb;
                LDSM4(b0, b1, b2, b3, bd);
#pragma unroll
                for (int mi = 0; mi < 4; mi++) {
                    MMA16816(acc[mi][ni * 2], a[mi][0], a[mi][1], a[mi][2], a[mi][3], b0, b1);
                    MMA16816(acc[mi][ni * 2 + 1], a[mi][0], a[mi][1], a[mi][2], a[mi][3], b2, b3);
                }
            }
        }
        __syncthreads();
    }

    int rbase = m0 + wm + (lane >> 2);
    int cbase = n0 + wn + 2 * (lane & 3);
#pragma unroll
    for (int mi = 0; mi < 4; mi++) {
#pragma unroll
        for (int half = 0; half < 2; half++) {
            int m = rbase + mi * 16 + half * 8;
            if (m >= M) continue;
            int orow = mode ? ((m & (Bb - 1)) * Ss + (m >> 4) + 1) : m;
            float* crow = C + (size_t)orow * N;
#pragma unroll
            for (int nj = 0; nj < 8; nj++) {
                int n = cbase + nj * 8;
                float2 v;
                v.x = acc[mi][nj][half * 2 + 0] + bias[n];
                v.y = acc[mi][nj][half * 2 + 1] + bias[n + 1];
                *(float2*)(crow + n) = v;
            }
        }
    }
}

// ---------------- persistent LSTM layer kernel ----------------
// 128 CTAs, each owns 8 hidden units (32 Whh rows: 4 gates x 8). Whh slice in
// smem for the whole layer; h staged to smem per step (__ldcg: L1 stale-bypass);
// c in smem; steps separated by a global atomic grid barrier; h double-buffered.
#define HS 1028  // padded row stride in floats (4112B: 2-phase worst-case banks)
#define LSTM_SMEM ((48 * HS + 32 * 17 + 128) * 4)

__global__ __launch_bounds__(256) void lstm_layer_kernel(
    const float* __restrict__ pre,     // [T*B, 4H]
    const float* __restrict__ Whh,     // [4H, H]
    const float* __restrict__ h_init,  // [B, H]
    const float* __restrict__ c_init,  // [B, H]
    float* __restrict__ hb0, float* __restrict__ hb1,  // global h double buffers
    float* __restrict__ y,             // [T*B, H] or null
    float* __restrict__ c_fin,         // [B, H] or null
    int T) {
    extern __shared__ float sm[];
    float* ws = sm;                 // 32 x HS
    float* hs = sm + 32 * HS;       // 16 x HS
    float* red = sm + 48 * HS;      // 32 x 17
    float* cs = red + 32 * 17;      // 128

    int tid = threadIdx.x;
    int j0 = blockIdx.x * 8;

    // Load Whh slice once: smem row r = g*8+jj -> global row g*H + j0 + jj
    for (int idx = tid; idx < 32 * 256; idx += 256) {
        int r = idx >> 8;
        int c4 = idx & 255;
        int g = r >> 3, jj = r & 7;
        float4 v = *(const float4*)(Whh + (size_t)(g * Hh + j0 + jj) * Hh + c4 * 4);
        *(float4*)(ws + r * HS + c4 * 4) = v;
    }
    if (tid < 128) {
        int m = tid & 15, jr = tid >> 4;
        cs[tid] = c_init[m * Hh + j0 + jr];
    }
    __syncthreads();

    int row = tid >> 3;  // 0..31 (gate g=row>>3, jj=row&7)
    int mp = tid & 7;
    const float* wrow = ws + row * HS;
    const float* h0p = hs + (2 * mp) * HS;
    const float* h1p = h0p + HS;

    for (int s = 0; s < T; s++) {
        // stage h[B,H] into smem (bypass L1: other SMs wrote it last step)
        const float* hsrc = (s == 0) ? h_init : ((s & 1) ? hb1 : hb0);
        for (int idx = tid; idx < 16 * 256; idx += 256) {
            int m = idx >> 8, c4 = idx & 255;
            float4 v = __ldcg((const float4*)(hsrc + (size_t)m * Hh + c4 * 4));
            *(float4*)(hs + m * HS + c4 * 4) = v;
        }
        __syncthreads();

        float acc0 = 0.f, acc1 = 0.f;
#pragma unroll 4
        for (int k = 0; k < Hh; k += 4) {
            float4 w = *(const float4*)(wrow + k);
            float4 a = *(const float4*)(h0p + k);
            float4 b = *(const float4*)(h1p + k);
            acc0 = fmaf(w.x, a.x, acc0); acc0 = fmaf(w.y, a.y, acc0);
            acc0 = fmaf(w.z, a.z, acc0); acc0 = fmaf(w.w, a.w, acc0);
            acc1 = fmaf(w.x, b.x, acc1); acc1 = fmaf(w.y, b.y, acc1);
            acc1 = fmaf(w.z, b.z, acc1); acc1 = fmaf(w.w, b.w, acc1);
        }
        red[row * 17 + 2 * mp] = acc0;
        red[row * 17 + 2 * mp + 1] = acc1;
        __syncthreads();

        if (tid < 128) {
            int m = tid & 15, jr = tid >> 4;
            const float* pm = pre + (size_t)(s * Bb + m) * G4;
            float pi = pm[0 * Hh + j0 + jr] + red[jr * 17 + m];
            float pf = pm[1 * Hh + j0 + jr] + red[(8 + jr) * 17 + m];
            float pg = pm[2 * Hh + j0 + jr] + red[(16 + jr) * 17 + m];
            float po = pm[3 * Hh + j0 + jr] + red[(24 + jr) * 17 + m];
            float iv = 1.0f / (1.0f + expf(-pi));
            float fv = 1.0f / (1.0f + expf(-pf));
            float gv = tanhf(pg);
            float ov = 1.0f / (1.0f + expf(-po));
            float cn = fv * cs[tid] + iv * gv;
            float hn = ov * tanhf(cn);
            cs[tid] = cn;
            float* hdst = ((s + 1) & 1) ? hb1 : hb0;
            hdst[m * Hh + j0 + jr] = hn;
            if (y) y[(size_t)(s * Bb + m) * Hh + j0 + jr] = hn;
        }
        __threadfence();
        __syncthreads();
        if (tid == 0) {
            atomicAdd(&g_bar, 1u);
            unsigned target = (unsigned)(s + 1) * 128u;
            while (*(volatile unsigned*)&g_bar < target) {}
            __threadfence();
        }
        __syncthreads();
    }

    if (c_fin && tid < 128) {
        int m = tid & 15, jr = tid >> 4;
        c_fin[m * Hh + j0 + jr] = cs[tid];
    }
}

// ---------------- host orchestration ----------------
static inline void split_w(const float* w, __nv_bfloat16* hi, __nv_bfloat16* lo, int n) {
    int n4 = n / 4;
    split4_kernel<<<(n4 + 255) / 256, 256>>>(w, hi, lo, n4);
}

static inline void gemm_tc(const __nv_bfloat16* Ah, const __nv_bfloat16* Al,
                           const __nv_bfloat16* Bh, const __nv_bfloat16* Bl,
                           const float* bias, float* C, int M, int N, int K, int mode) {
    dim3 grid(N / 128, (M + 127) / 128);
    gemm_mma_kernel<<<grid, 128, GEMM_SMEM>>>(Ah, Al, Bh, Bl, bias, C, M, N, K, mode);
}

static inline void run_lstm_layer(const float* pre, const float* Whh, const float* h_init,
                                  const float* c_init, float* hb0, float* hb1, float* y,
                                  float* c_fin, int T) {
    zero_bar_kernel<<<1, 1>>>();
    lstm_layer_kernel<<<128, 256, LSTM_SMEM>>>(pre, Whh, h_init, c_init, hb0, hb1, y,
                                               c_fin, T);
}

extern "C" void kernel_launch(void* const* d_in, const int* in_sizes, int n_in,
                              void* d_out, int out_size) {
    const int* src = (const int*)d_in[0];
    const int* trg = (const int*)d_in[1];
    const float* enc_emb = (const float*)d_in[2];
    const float* dec_emb = (const float*)d_in[3];
    const float* enc_Wih0 = (const float*)d_in[4];
    const float* enc_Whh0 = (const float*)d_in[5];
    const float* enc_b0 = (const float*)d_in[6];
    const float* enc_Wih1 = (const float*)d_in[7];
    const float* enc_Whh1 = (const float*)d_in[8];
    const float* enc_b1 = (const float*)d_in[9];
    const float* dec_Wih0 = (const float*)d_in[10];
    const float* dec_Whh0 = (const float*)d_in[11];
    const float* dec_b0 = (const float*)d_in[12];
    const float* dec_Wih1 = (const float*)d_in[13];
    const float* dec_Whh1 = (const float*)d_in[14];
    const float* dec_b1 = (const float*)d_in[15];
    const float* fc_W = (const float*)d_in[16];
    const float* fc_b = (const float*)d_in[17];
    float* out = (float*)d_out;

    cudaFuncSetAttribute(gemm_mma_kernel, cudaFuncAttributeMaxDynamicSharedMemorySize,
                         GEMM_SMEM);
    cudaFuncSetAttribute(lstm_layer_kernel, cudaFuncAttributeMaxDynamicSharedMemorySize,
                         LSTM_SMEM);

    float *pre, *seq, *hA, *hB, *cb, *h0f, *c0f, *h1f, *c1f;
    __nv_bfloat16 *ah, *al, *wh, *wl;
    cudaGetSymbolAddress((void**)&pre, g_pre);
    cudaGetSymbolAddress((void**)&seq, g_seq);
    cudaGetSymbolAddress((void**)&ah, g_ah);
    cudaGetSymbolAddress((void**)&al, g_al);
    cudaGetSymbolAddress((void**)&wh, g_wh);
    cudaGetSymbolAddress((void**)&wl, g_wl);
    cudaGetSymbolAddress((void**)&hA, g_hA);
    cudaGetSymbolAddress((void**)&hB, g_hB);
    cudaGetSymbolAddress((void**)&cb, g_c);
    cudaGetSymbolAddress((void**)&h0f, g_h0f);
    cudaGetSymbolAddress((void**)&c0f, g_c0f);
    cudaGetSymbolAddress((void**)&h1f, g_h1f);
    cudaGetSymbolAddress((void**)&c1f, g_c1f);

    const int NST = Bb * Hh;

    // ================= ENCODER layer 0 =================
    {
        int total = Ss * Bb * (Ee / 2);
        gather_split_kernel<<<(total + 255) / 256, 256>>>(src, enc_emb, ah, al, Ss);
    }
    split_w(enc_Wih0, wh, wl, G4 * Ee);
    gemm_tc(ah, al, wh, wl, enc_b0, pre, Bb * Ss, G4, Ee, 0);
    zero_kernel<<<(NST + 255) / 256, 256>>>(hA, NST);
    zero_kernel<<<(NST + 255) / 256, 256>>>(cb, NST);
    run_lstm_layer(pre, enc_Whh0, hA, cb, hA, hB, seq, c0f, Ss);
    // T=128 -> final h in hA (written at step 127 to buf[(128)&1]=hA)
    copy_kernel<<<(NST + 255) / 256, 256>>>(h0f, hA, NST);

    // ================= ENCODER layer 1 (only final state needed) =================
    split_w(seq, ah, al, Bb * Ss * Hh);
    split_w(enc_Wih1, wh, wl, G4 * Hh);
    gemm_tc(ah, al, wh, wl, enc_b1, pre, Bb * Ss, G4, Hh, 0);
    zero_kernel<<<(NST + 255) / 256, 256>>>(hA, NST);
    zero_kernel<<<(NST + 255) / 256, 256>>>(cb, NST);
    run_lstm_layer(pre, enc_Whh1, hA, cb, hA, hB, (float*)0, c1f, Ss);
    copy_kernel<<<(NST + 255) / 256, 256>>>(h1f, hA, NST);

    // ================= DECODER layer 0 (T = 127) =================
    const int Td = Ss - 1;
    {
        int total = Td * Bb * (Ee / 2);
        gather_split_kernel<<<(total + 255) / 256, 256>>>(trg, dec_emb, ah, al, Td);
    }
    split_w(dec_Wih0, wh, wl, G4 * Ee);
    gemm_tc(ah, al, wh, wl, dec_b0, pre, Bb * Td, G4, Ee, 0);
    run_lstm_layer(pre, dec_Whh0, h0f, c0f, hA, hB, seq, (float*)0, Td);

    // ================= DECODER layer 1 =================
    split_w(seq, ah, al, Bb * Td * Hh);
    split_w(dec_Wih1, wh, wl, G4 * Hh);
    gemm_tc(ah, al, wh, wl, dec_b1, pre, Bb * Td, G4, Hh, 0);
    run_lstm_layer(pre, dec_Whh1, h1f, c1f, hA, hB, seq, (float*)0, Td);

    // ================= Classifier =================
    split_w(seq, ah, al, Bb * Td * Hh);
    split_w(fc_W, wh, wl, Vv * Hh);
    zero_t0_kernel<<<(Bb * Vv + 255) / 256, 256>>>(out);
    gemm_tc(ah, al, wh, wl, fc_b, out, Bb * Td, Vv, Hh, 1);
}